// round 12
// baseline (speedup 1.0000x reference)
#include <cuda_runtime.h>
#include <cstdint>

// ContMlpPerFeature via mma.sync tf32 (sm_103-portable; tcgen05 needs the
// 'a' target this harness does not emit):
//   per f: H1 = relu(r_f[B,64] @ W1_f[64,128] + b1)    (tensor core)
//          y  = relu(H1 . W2_f + b2)                   (fused, in registers)
//   out[b,f] = (X[b,f], y)

constexpr int Fdim   = 32;
constexpr int Ddim   = 64;    // K
constexpr int Hdim   = 128;   // N
constexpr int TILE_M = 128;   // rows per CTA iteration
constexpr int THREADS = 128;  // 4 warps, 32 rows each
constexpr int CPF    = 32;    // CTAs per feature
constexpr int RS     = 68;    // smem row stride (floats) -> conflict-free frags

// dynamic smem layout (float offsets)
constexpr int OFF_W1 = 0;                   // W1^T [h=128][d=64], stride 68
constexpr int OFF_A  = OFF_W1 + 128 * RS;   // A tile [row=128][d=64], stride 68
constexpr int OFF_B1 = OFF_A + 128 * RS;
constexpr int OFF_W2 = OFF_B1 + Hdim;
constexpr int SM_FLOATS = OFF_W2 + Hdim;
constexpr int SM_BYTES  = SM_FLOATS * 4;    // 70,656 B

__device__ __forceinline__ uint32_t f2tf32(float x) {
    uint32_t r;
    asm("cvt.rna.tf32.f32 %0, %1;" : "=r"(r) : "f"(x));
    return r;
}

__device__ __forceinline__ void mma_tf32(float c[4], const uint32_t a[4],
                                         const uint32_t b[2]) {
    asm volatile(
        "mma.sync.aligned.m16n8k8.row.col.f32.tf32.tf32.f32 "
        "{%0,%1,%2,%3}, {%4,%5,%6,%7}, {%8,%9}, {%0,%1,%2,%3};"
        : "+f"(c[0]), "+f"(c[1]), "+f"(c[2]), "+f"(c[3])
        : "r"(a[0]), "r"(a[1]), "r"(a[2]), "r"(a[3]), "r"(b[0]), "r"(b[1]));
}

__global__ __launch_bounds__(THREADS)
void cont_mlp_mma_kernel(const float* __restrict__ X,
                         const float* __restrict__ r_,
                         const float* __restrict__ W1,
                         const float* __restrict__ b1,
                         const float* __restrict__ W2,
                         const float* __restrict__ b2,
                         float* __restrict__ out,
                         int B)
{
    extern __shared__ float sm[];
    uint32_t* W1u = reinterpret_cast<uint32_t*>(sm + OFF_W1);
    uint32_t* Au  = reinterpret_cast<uint32_t*>(sm + OFF_A);
    float*    b1s = sm + OFF_B1;
    float*    w2s = sm + OFF_W2;

    const int tid  = threadIdx.x;
    const int wid  = tid >> 5;
    const int lane = tid & 31;
    const int g    = lane >> 2;   // groupID (row within frag)
    const int lr   = lane & 3;
    const int f    = blockIdx.y;
    const int c    = blockIdx.x;

    const int tpc = B / (TILE_M * CPF);   // tiles per CTA (=4 for B=16384)

    // ---- stage W1^T (with tf32 rounding), b1, W2 ----
    const float* W1f = W1 + (size_t)f * Ddim * Hdim;
    #pragma unroll
    for (int i = tid; i < Ddim * Hdim; i += THREADS) {
        const int d = i >> 7;        // Hdim = 128
        const int h = i & 127;
        W1u[h * RS + d] = f2tf32(W1f[i]);
    }
    b1s[tid] = b1[(size_t)f * Hdim + tid];
    w2s[tid] = W2[(size_t)f * Hdim + tid];
    const float b2v = __ldg(b2 + f);

    const int mbase = wid * 32;
    const size_t row_stride = (size_t)Fdim * Ddim;   // floats between batch rows

    for (int t = 0; t < tpc; t++) {
        const int tile = c * tpc + t;

        // ---- stage A tile: r_[tile*128 .. +128, f, :] -> tf32, stride RS ----
        const float* src = r_ + ((size_t)tile * TILE_M * Fdim + f) * Ddim;
        __syncthreads();   // previous iteration's reads of Au complete
        #pragma unroll
        for (int i = 0; i < (TILE_M * Ddim / 4) / THREADS; i++) {
            const int idx = tid + i * THREADS;
            const int row = idx >> 4;
            const int q   = idx & 15;
            const float4 v =
                *reinterpret_cast<const float4*>(src + (size_t)row * row_stride + q * 4);
            uint4 o;
            o.x = f2tf32(v.x); o.y = f2tf32(v.y);
            o.z = f2tf32(v.z); o.w = f2tf32(v.w);
            *reinterpret_cast<uint4*>(Au + row * RS + q * 4) = o;
        }
        __syncthreads();

        // ---- compute: 32 rows per warp, N in two 64-wide chunks ----
        float yp[4] = {0.f, 0.f, 0.f, 0.f};   // [m][rowhalf]

        #pragma unroll
        for (int ch = 0; ch < 2; ch++) {
            const int n0 = ch * 64;
            float acc[2][8][4] = {};

            #pragma unroll
            for (int k = 0; k < 8; k++) {
                const int acol = k * 8 + lr;
                const uint32_t* Ab = Au + (mbase + g) * RS + acol;
                uint32_t a0[4], a1[4];
                a0[0] = Ab[0];           a0[1] = Ab[8 * RS];
                a0[2] = Ab[4];           a0[3] = Ab[8 * RS + 4];
                a1[0] = Ab[16 * RS];     a1[1] = Ab[24 * RS];
                a1[2] = Ab[16 * RS + 4]; a1[3] = Ab[24 * RS + 4];

                const uint32_t* Bb = W1u + (n0 + g) * RS + acol;
                #pragma unroll
                for (int nt = 0; nt < 8; nt++) {
                    uint32_t b[2];
                    b[0] = Bb[nt * 8 * RS];
                    b[1] = Bb[nt * 8 * RS + 4];
                    mma_tf32(acc[0][nt], a0, b);
                    mma_tf32(acc[1][nt], a1, b);
                }
            }

            // epilogue: relu(acc + b1) . W2, accumulated per lane
            #pragma unroll
            for (int nt = 0; nt < 8; nt++) {
                const int col = n0 + nt * 8 + 2 * lr;
                const float2 bb = *reinterpret_cast<const float2*>(b1s + col);
                const float2 ww = *reinterpret_cast<const float2*>(w2s + col);
                #pragma unroll
                for (int m = 0; m < 2; m++) {
                    const float h0 = fmaxf(acc[m][nt][0] + bb.x, 0.f);
                    const float h1 = fmaxf(acc[m][nt][1] + bb.y, 0.f);
                    const float h2 = fmaxf(acc[m][nt][2] + bb.x, 0.f);
                    const float h3 = fmaxf(acc[m][nt][3] + bb.y, 0.f);
                    yp[m * 2 + 0] = fmaf(h0, ww.x, fmaf(h1, ww.y, yp[m * 2 + 0]));
                    yp[m * 2 + 1] = fmaf(h2, ww.x, fmaf(h3, ww.y, yp[m * 2 + 1]));
                }
            }
        }

        // quad reduction over lane%4 (groupID preserved by xor 1,2)
        #pragma unroll
        for (int i = 0; i < 4; i++) {
            yp[i] += __shfl_xor_sync(0xffffffffu, yp[i], 1);
            yp[i] += __shfl_xor_sync(0xffffffffu, yp[i], 2);
        }

        if (lr == 0) {
            const int rowbase = tile * TILE_M + mbase + g;
            #pragma unroll
            for (int m = 0; m < 2; m++) {
                #pragma unroll
                for (int hh = 0; hh < 2; hh++) {
                    const int r = rowbase + m * 16 + hh * 8;
                    const float y = fmaxf(yp[m * 2 + hh] + b2v, 0.f);
                    const size_t oi = (size_t)r * Fdim + f;
                    reinterpret_cast<float2*>(out)[oi] = make_float2(X[oi], y);
                }
            }
        }
    }
}

extern "C" void kernel_launch(void* const* d_in, const int* in_sizes, int n_in,
                              void* d_out, int out_size)
{
    const float* X  = (const float*)d_in[0];
    const float* r_ = (const float*)d_in[1];
    const float* W1 = (const float*)d_in[2];
    const float* b1 = (const float*)d_in[3];
    const float* W2 = (const float*)d_in[4];
    const float* b2 = (const float*)d_in[5];
    float* out = (float*)d_out;

    const int B = in_sizes[0] / Fdim;

    cudaFuncSetAttribute(cont_mlp_mma_kernel,
                         cudaFuncAttributeMaxDynamicSharedMemorySize, SM_BYTES);

    dim3 grid(CPF, Fdim);
    cont_mlp_mma_kernel<<<grid, THREADS, SM_BYTES>>>(X, r_, W1, b1, W2, b2, out, B);
}

// round 13
// speedup vs baseline: 1.0040x; 1.0040x over previous
#include <cuda_runtime.h>
#include <cstdint>

// ContMlpPerFeature via mma.sync tf32 (sm_103-portable; tcgen05 needs the
// 'a' target this harness does not emit):
//   per f: H1 = relu(r_f[B,64] @ W1_f[64,128] + b1)    (tensor core)
//          y  = relu(H1 . W2_f + b2)                   (fused, in registers)
//   out[b,f] = (X[b,f], y)

constexpr int Fdim   = 32;
constexpr int Ddim   = 64;    // K
constexpr int Hdim   = 128;   // N
constexpr int TILE_M = 128;   // rows per CTA iteration
constexpr int THREADS = 128;  // 4 warps, 32 rows each
constexpr int CPF    = 32;    // CTAs per feature
constexpr int RS     = 68;    // smem row stride (floats) -> conflict-free frags

// dynamic smem layout (float offsets)
constexpr int OFF_W1 = 0;                   // W1^T [h=128][d=64], stride 68
constexpr int OFF_A  = OFF_W1 + 128 * RS;   // A tile [row=128][d=64], stride 68
constexpr int OFF_B1 = OFF_A + 128 * RS;
constexpr int OFF_W2 = OFF_B1 + Hdim;
constexpr int SM_FLOATS = OFF_W2 + Hdim;
constexpr int SM_BYTES  = SM_FLOATS * 4;    // 70,656 B

__device__ __forceinline__ uint32_t f2tf32(float x) {
    uint32_t r;
    asm("cvt.rna.tf32.f32 %0, %1;" : "=r"(r) : "f"(x));
    return r;
}

__device__ __forceinline__ void mma_tf32(float c[4], const uint32_t a[4],
                                         const uint32_t b[2]) {
    asm volatile(
        "mma.sync.aligned.m16n8k8.row.col.f32.tf32.tf32.f32 "
        "{%0,%1,%2,%3}, {%4,%5,%6,%7}, {%8,%9}, {%0,%1,%2,%3};"
        : "+f"(c[0]), "+f"(c[1]), "+f"(c[2]), "+f"(c[3])
        : "r"(a[0]), "r"(a[1]), "r"(a[2]), "r"(a[3]), "r"(b[0]), "r"(b[1]));
}

__global__ __launch_bounds__(THREADS)
void cont_mlp_mma_kernel(const float* __restrict__ X,
                         const float* __restrict__ r_,
                         const float* __restrict__ W1,
                         const float* __restrict__ b1,
                         const float* __restrict__ W2,
                         const float* __restrict__ b2,
                         float* __restrict__ out,
                         int B)
{
    extern __shared__ float sm[];
    uint32_t* W1u = reinterpret_cast<uint32_t*>(sm + OFF_W1);
    uint32_t* Au  = reinterpret_cast<uint32_t*>(sm + OFF_A);
    float*    b1s = sm + OFF_B1;
    float*    w2s = sm + OFF_W2;

    const int tid  = threadIdx.x;
    const int wid  = tid >> 5;
    const int lane = tid & 31;
    const int g    = lane >> 2;   // groupID (row within frag)
    const int lr   = lane & 3;
    const int f    = blockIdx.y;
    const int c    = blockIdx.x;

    const int tpc = B / (TILE_M * CPF);   // tiles per CTA (=4 for B=16384)

    // ---- stage W1^T (with tf32 rounding), b1, W2 ----
    const float* W1f = W1 + (size_t)f * Ddim * Hdim;
    #pragma unroll
    for (int i = tid; i < Ddim * Hdim; i += THREADS) {
        const int d = i >> 7;        // Hdim = 128
        const int h = i & 127;
        W1u[h * RS + d] = f2tf32(W1f[i]);
    }
    b1s[tid] = b1[(size_t)f * Hdim + tid];
    w2s[tid] = W2[(size_t)f * Hdim + tid];
    const float b2v = __ldg(b2 + f);

    const int mbase = wid * 32;
    const size_t row_stride = (size_t)Fdim * Ddim;   // floats between batch rows

    for (int t = 0; t < tpc; t++) {
        const int tile = c * tpc + t;

        // ---- stage A tile: r_[tile*128 .. +128, f, :] -> tf32, stride RS ----
        const float* src = r_ + ((size_t)tile * TILE_M * Fdim + f) * Ddim;
        __syncthreads();   // previous iteration's reads of Au complete
        #pragma unroll
        for (int i = 0; i < (TILE_M * Ddim / 4) / THREADS; i++) {
            const int idx = tid + i * THREADS;
            const int row = idx >> 4;
            const int q   = idx & 15;
            const float4 v =
                *reinterpret_cast<const float4*>(src + (size_t)row * row_stride + q * 4);
            uint4 o;
            o.x = f2tf32(v.x); o.y = f2tf32(v.y);
            o.z = f2tf32(v.z); o.w = f2tf32(v.w);
            *reinterpret_cast<uint4*>(Au + row * RS + q * 4) = o;
        }
        __syncthreads();

        // ---- compute: 32 rows per warp, N in two 64-wide chunks ----
        float yp[4] = {0.f, 0.f, 0.f, 0.f};   // [m][rowhalf]

        #pragma unroll
        for (int ch = 0; ch < 2; ch++) {
            const int n0 = ch * 64;
            float acc[2][8][4] = {};

            #pragma unroll
            for (int k = 0; k < 8; k++) {
                const int acol = k * 8 + lr;
                const uint32_t* Ab = Au + (mbase + g) * RS + acol;
                uint32_t a0[4], a1[4];
                a0[0] = Ab[0];           a0[1] = Ab[8 * RS];
                a0[2] = Ab[4];           a0[3] = Ab[8 * RS + 4];
                a1[0] = Ab[16 * RS];     a1[1] = Ab[24 * RS];
                a1[2] = Ab[16 * RS + 4]; a1[3] = Ab[24 * RS + 4];

                const uint32_t* Bb = W1u + (n0 + g) * RS + acol;
                #pragma unroll
                for (int nt = 0; nt < 8; nt++) {
                    uint32_t b[2];
                    b[0] = Bb[nt * 8 * RS];
                    b[1] = Bb[nt * 8 * RS + 4];
                    mma_tf32(acc[0][nt], a0, b);
                    mma_tf32(acc[1][nt], a1, b);
                }
            }

            // epilogue: relu(acc + b1) . W2, accumulated per lane
            #pragma unroll
            for (int nt = 0; nt < 8; nt++) {
                const int col = n0 + nt * 8 + 2 * lr;
                const float2 bb = *reinterpret_cast<const float2*>(b1s + col);
                const float2 ww = *reinterpret_cast<const float2*>(w2s + col);
                #pragma unroll
                for (int m = 0; m < 2; m++) {
                    const float h0 = fmaxf(acc[m][nt][0] + bb.x, 0.f);
                    const float h1 = fmaxf(acc[m][nt][1] + bb.y, 0.f);
                    const float h2 = fmaxf(acc[m][nt][2] + bb.x, 0.f);
                    const float h3 = fmaxf(acc[m][nt][3] + bb.y, 0.f);
                    yp[m * 2 + 0] = fmaf(h0, ww.x, fmaf(h1, ww.y, yp[m * 2 + 0]));
                    yp[m * 2 + 1] = fmaf(h2, ww.x, fmaf(h3, ww.y, yp[m * 2 + 1]));
                }
            }
        }

        // quad reduction over lane%4 (groupID preserved by xor 1,2)
        #pragma unroll
        for (int i = 0; i < 4; i++) {
            yp[i] += __shfl_xor_sync(0xffffffffu, yp[i], 1);
            yp[i] += __shfl_xor_sync(0xffffffffu, yp[i], 2);
        }

        if (lr == 0) {
            const int rowbase = tile * TILE_M + mbase + g;
            #pragma unroll
            for (int m = 0; m < 2; m++) {
                #pragma unroll
                for (int hh = 0; hh < 2; hh++) {
                    const int r = rowbase + m * 16 + hh * 8;
                    const float y = fmaxf(yp[m * 2 + hh] + b2v, 0.f);
                    const size_t oi = (size_t)r * Fdim + f;
                    reinterpret_cast<float2*>(out)[oi] = make_float2(X[oi], y);
                }
            }
        }
    }
}

extern "C" void kernel_launch(void* const* d_in, const int* in_sizes, int n_in,
                              void* d_out, int out_size)
{
    const float* X  = (const float*)d_in[0];
    const float* r_ = (const float*)d_in[1];
    const float* W1 = (const float*)d_in[2];
    const float* b1 = (const float*)d_in[3];
    const float* W2 = (const float*)d_in[4];
    const float* b2 = (const float*)d_in[5];
    float* out = (float*)d_out;

    const int B = in_sizes[0] / Fdim;

    cudaFuncSetAttribute(cont_mlp_mma_kernel,
                         cudaFuncAttributeMaxDynamicSharedMemorySize, SM_BYTES);

    dim3 grid(CPF, Fdim);
    cont_mlp_mma_kernel<<<grid, THREADS, SM_BYTES>>>(X, r_, W1, b1, W2, b2, out, B);
}